// round 14
// baseline (speedup 1.0000x reference)
#include <cuda_runtime.h>
#include <cuda_fp16.h>
#include <cstdint>

// NonLocalBlock B=8, N=4096, M=2048, C=256, d=128
#define NB 8
#define NN 4096
#define NM 2048
#define NC 256
#define ND 128

__device__ float  g_theta[NB * NN * ND];
__device__ float  g_phi  [NB * NN * ND];
__device__ float  g_gg   [NB * NN * ND];
__device__ float  g_phiP [NB * NM * ND];         // [b][m][d]
__device__ __half g_gPt  [NB * ND * NM];         // [b][d][m], fp16
__device__ float  g_S    [NB * NN * NM];         // raw logits (256 MB)
__device__ float  g_pmax [NB * NN * 32];         // per-row partial maxes
__device__ float  g_y    [NB * NN * ND];

// ---------------------------------------------------------------------------
__device__ __forceinline__ void mma_f16(float (&d)[4],
                                        uint32_t a0, uint32_t a1, uint32_t a2, uint32_t a3,
                                        uint32_t b0, uint32_t b1) {
    asm volatile(
        "mma.sync.aligned.m16n8k16.row.col.f32.f16.f16.f32 "
        "{%0,%1,%2,%3}, {%4,%5,%6,%7}, {%8,%9}, {%0,%1,%2,%3};"
        : "+f"(d[0]), "+f"(d[1]), "+f"(d[2]), "+f"(d[3])
        : "r"(a0), "r"(a1), "r"(a2), "r"(a3), "r"(b0), "r"(b1));
}
__device__ __forceinline__ uint32_t smem_u32(const void* p) {
    uint32_t a;
    asm("{ .reg .u64 t; cvta.to.shared.u64 t, %1; cvt.u32.u64 %0, t; }" : "=r"(a) : "l"(p));
    return a;
}
__device__ __forceinline__ void cp_async16(uint32_t dst, const void* src) {
    asm volatile("cp.async.cg.shared.global [%0], [%1], 16;" :: "r"(dst), "l"(src) : "memory");
}
#define CP_COMMIT() asm volatile("cp.async.commit_group;" ::: "memory")
#define CP_WAIT1()  asm volatile("cp.async.wait_group 1;" ::: "memory")

__device__ __forceinline__ uint32_t h2pack(float a, float b) {
    __half2 h = __floats2half2_rn(a, b);
    return *(uint32_t*)&h;
}
// split 4 floats into hi(2xhalf2) and lo(2xhalf2)
__device__ __forceinline__ void split4(float4 v, uint2& hi, uint2& lo) {
    __half h0 = __float2half_rn(v.x), h1 = __float2half_rn(v.y);
    __half h2 = __float2half_rn(v.z), h3 = __float2half_rn(v.w);
    float l0 = v.x - __half2float(h0), l1 = v.y - __half2float(h1);
    float l2 = v.z - __half2float(h2), l3 = v.w - __half2float(h3);
    __half2 hh0 = __halves2half2(h0, h1), hh1 = __halves2half2(h2, h3);
    hi.x = *(uint32_t*)&hh0; hi.y = *(uint32_t*)&hh1;
    lo.x = h2pack(l0, l1);   lo.y = h2pack(l2, l3);
}

#define W36 36                   // split tile stride in u32 words
#define OFF_AH 0
#define OFF_AL (128 * W36)
#define OFF_BH (2 * 128 * W36)
#define OFF_BL (3 * 128 * W36)
#define GEMM_SMEM_U32 (4 * 128 * W36)   // 73728 B

// ===========================================================================
// Split-fp16 GEMM mainloop body (shared shape): warp tile 32x64, mt=2, nt=8,
// K chunk = 64 (4 k16 steps).
// ===========================================================================
#define GEMM_MAINLOOP(SMU)                                                     \
    _Pragma("unroll")                                                          \
    for (int kst = 0; kst < 4; kst++) {                                        \
        int kh = kst * 8;                                                      \
        uint32_t ah[2][4], al[2][4];                                           \
        _Pragma("unroll")                                                      \
        for (int mt = 0; mt < 2; mt++) {                                       \
            int base = (r0 + 16 * mt + g) * W36 + kh + t;                      \
            ah[mt][0] = SMU[OFF_AH + base];                                    \
            ah[mt][1] = SMU[OFF_AH + base + 8 * W36];                          \
            ah[mt][2] = SMU[OFF_AH + base + 4];                                \
            ah[mt][3] = SMU[OFF_AH + base + 8 * W36 + 4];                      \
            al[mt][0] = SMU[OFF_AL + base];                                    \
            al[mt][1] = SMU[OFF_AL + base + 8 * W36];                          \
            al[mt][2] = SMU[OFF_AL + base + 4];                                \
            al[mt][3] = SMU[OFF_AL + base + 8 * W36 + 4];                      \
        }                                                                      \
        _Pragma("unroll")                                                      \
        for (int nt = 0; nt < 8; nt++) {                                       \
            int gb = (c0 + 8 * nt + g) * W36 + kh + t;                         \
            uint32_t bh0 = SMU[OFF_BH + gb], bh1 = SMU[OFF_BH + gb + 4];       \
            uint32_t bl0 = SMU[OFF_BL + gb], bl1 = SMU[OFF_BL + gb + 4];       \
            _Pragma("unroll")                                                  \
            for (int mt = 0; mt < 2; mt++) {                                   \
                mma_f16(acc[mt][nt], ah[mt][0], ah[mt][1], ah[mt][2], ah[mt][3], bh0, bh1); \
                mma_f16(acc[mt][nt], ah[mt][0], ah[mt][1], ah[mt][2], ah[mt][3], bl0, bl1); \
                mma_f16(acc[mt][nt], al[mt][0], al[mt][1], al[mt][2], al[mt][3], bh0, bh1); \
            }                                                                  \
        }                                                                      \
    }

// ===========================================================================
// Projection GEMM (split-fp16): C[32768,128] = x[32768,256] @ W[256,128], x3
// ===========================================================================
__global__ __launch_bounds__(256, 2) void proj_kernel(
    const float* __restrict__ x, const float* __restrict__ Wt,
    const float* __restrict__ Wp, const float* __restrict__ Wg)
{
    extern __shared__ uint32_t smu[];

    const float* W; float* out;
    if (blockIdx.z == 0)      { W = Wt; out = g_theta; }
    else if (blockIdx.z == 1) { W = Wp; out = g_phi; }
    else                      { W = Wg; out = g_gg; }

    int tid = threadIdx.x, row0 = blockIdx.x * 128;
    int lane = tid & 31, g = lane >> 2, t = lane & 3;
    int wid = tid >> 5, wr = wid >> 1, wc = wid & 1;
    int r0 = wr * 32, c0 = wc * 64;

    float acc[2][8][4];
#pragma unroll
    for (int mt = 0; mt < 2; mt++)
#pragma unroll
        for (int nt = 0; nt < 8; nt++)
#pragma unroll
            for (int i = 0; i < 4; i++) acc[mt][nt][i] = 0.f;

#pragma unroll 1
    for (int kc = 0; kc < 4; kc++) {
        int k0 = kc * 64;
        __syncthreads();
        // A: x rows (contiguous k), split-pack
#pragma unroll
        for (int q = 0; q < 8; q++) {
            int li = q * 256 + tid, r = li >> 4, c = (li & 15) * 4;
            float4 v = *(const float4*)(x + (size_t)(row0 + r) * NC + k0 + c);
            uint2 hi, lo; split4(v, hi, lo);
            *(uint2*)&smu[OFF_AH + r * W36 + (c >> 1)] = hi;
            *(uint2*)&smu[OFF_AL + r * W36 + (c >> 1)] = lo;
        }
        // B: W[k][n] -> n-major split tiles
#pragma unroll
        for (int q = 0; q < 8; q++) {
            int li = q * 256 + tid, n = li & 127, kq = li >> 7;
            float4 v;
            v.x = W[(size_t)(k0 + kq * 4 + 0) * ND + n];
            v.y = W[(size_t)(k0 + kq * 4 + 1) * ND + n];
            v.z = W[(size_t)(k0 + kq * 4 + 2) * ND + n];
            v.w = W[(size_t)(k0 + kq * 4 + 3) * ND + n];
            uint2 hi, lo; split4(v, hi, lo);
            *(uint2*)&smu[OFF_BH + n * W36 + kq * 2] = hi;
            *(uint2*)&smu[OFF_BL + n * W36 + kq * 2] = lo;
        }
        __syncthreads();
        GEMM_MAINLOOP(smu)
    }
#pragma unroll
    for (int mt = 0; mt < 2; mt++) {
        float* O0 = out + (size_t)(row0 + r0 + 16 * mt + g) * ND + c0;
        float* O1 = O0 + 8 * (size_t)ND;
#pragma unroll
        for (int nt = 0; nt < 8; nt++) {
            *(float2*)(O0 + 8 * nt + 2 * t) = make_float2(acc[mt][nt][0], acc[mt][nt][1]);
            *(float2*)(O1 + 8 * nt + 2 * t) = make_float2(acc[mt][nt][2], acc[mt][nt][3]);
        }
    }
}

// ===========================================================================
// MaxPool(2): phi -> phiP (fp32), g -> gPt (transposed, fp16)
// ===========================================================================
__global__ __launch_bounds__(256) void pool_kernel()
{
    int idx4 = blockIdx.x * 256 + threadIdx.x;
    int total4 = NB * NM * ND / 4;
    if (idx4 >= total4) return;
    int d4 = idx4 % (ND / 4);
    int r  = (idx4 / (ND / 4)) % NM;
    int b  = idx4 / ((ND / 4) * NM);
    int src = ((b * NN + 2 * r) * ND) / 4 + d4;
    const float4* p = (const float4*)g_phi;
    const float4* g = (const float4*)g_gg;
    float4 a = p[src], a2 = p[src + ND / 4];
    float4 c = g[src], c2 = g[src + ND / 4];
    ((float4*)g_phiP)[idx4] = make_float4(fmaxf(a.x, a2.x), fmaxf(a.y, a2.y),
                                          fmaxf(a.z, a2.z), fmaxf(a.w, a2.w));
    int d0 = d4 * 4;
    g_gPt[(b * ND + d0 + 0) * NM + r] = __float2half(fmaxf(c.x, c2.x));
    g_gPt[(b * ND + d0 + 1) * NM + r] = __float2half(fmaxf(c.y, c2.y));
    g_gPt[(b * ND + d0 + 2) * NM + r] = __float2half(fmaxf(c.z, c2.z));
    g_gPt[(b * ND + d0 + 3) * NM + r] = __float2half(fmaxf(c.w, c2.w));
}

// ===========================================================================
// GEMM1 (split-fp16): S_raw = theta @ phiP^T + partial-max epilogue
// ===========================================================================
__global__ __launch_bounds__(256, 2) void qk_kernel()
{
    extern __shared__ uint32_t smu[];

    int tid = threadIdx.x;
    int b = blockIdx.z, q0 = blockIdx.x * 128, m0 = blockIdx.y * 128;
    const float* Ap = g_theta + (size_t)(b * NN + q0) * ND;
    const float* Bp = g_phiP + (size_t)(b * NM + m0) * ND;

    int lane = tid & 31, g = lane >> 2, t = lane & 3;
    int wid = tid >> 5, wr = wid >> 1, wc = wid & 1;
    int r0 = wr * 32, c0 = wc * 64;

    float acc[2][8][4];
#pragma unroll
    for (int mt = 0; mt < 2; mt++)
#pragma unroll
        for (int nt = 0; nt < 8; nt++)
#pragma unroll
            for (int i = 0; i < 4; i++) acc[mt][nt][i] = 0.f;

#pragma unroll 1
    for (int kc = 0; kc < 2; kc++) {
        int k0 = kc * 64;
        __syncthreads();
#pragma unroll
        for (int q = 0; q < 8; q++) {
            int li = q * 256 + tid, r = li >> 4, c = (li & 15) * 4;
            float4 va = *(const float4*)(Ap + (size_t)r * ND + k0 + c);
            uint2 hi, lo; split4(va, hi, lo);
            *(uint2*)&smu[OFF_AH + r * W36 + (c >> 1)] = hi;
            *(uint2*)&smu[OFF_AL + r * W36 + (c >> 1)] = lo;
            float4 vb = *(const float4*)(Bp + (size_t)r * ND + k0 + c);
            split4(vb, hi, lo);
            *(uint2*)&smu[OFF_BH + r * W36 + (c >> 1)] = hi;
            *(uint2*)&smu[OFF_BL + r * W36 + (c >> 1)] = lo;
        }
        __syncthreads();
        GEMM_MAINLOOP(smu)
    }
    // write RAW logits + per-row partial maxes
#pragma unroll
    for (int mt = 0; mt < 2; mt++) {
        size_t ra = (size_t)(b * NN + q0 + r0 + 16 * mt + g);
        float* So0 = g_S + ra * NM + m0 + c0;
        float* So1 = So0 + 8 * (size_t)NM;
        float mx0 = -1e30f, mx1 = -1e30f;
#pragma unroll
        for (int nt = 0; nt < 8; nt++) {
            *(float2*)(So0 + 8 * nt + 2 * t) = make_float2(acc[mt][nt][0], acc[mt][nt][1]);
            *(float2*)(So1 + 8 * nt + 2 * t) = make_float2(acc[mt][nt][2], acc[mt][nt][3]);
            mx0 = fmaxf(mx0, fmaxf(acc[mt][nt][0], acc[mt][nt][1]));
            mx1 = fmaxf(mx1, fmaxf(acc[mt][nt][2], acc[mt][nt][3]));
        }
        mx0 = fmaxf(mx0, __shfl_xor_sync(0xFFFFFFFF, mx0, 1));
        mx0 = fmaxf(mx0, __shfl_xor_sync(0xFFFFFFFF, mx0, 2));
        mx1 = fmaxf(mx1, __shfl_xor_sync(0xFFFFFFFF, mx1, 1));
        mx1 = fmaxf(mx1, __shfl_xor_sync(0xFFFFFFFF, mx1, 2));
        if (t == 0) {
            g_pmax[ra * 32 + blockIdx.y * 2 + wc]       = mx0;
            g_pmax[(ra + 8) * 32 + blockIdx.y * 2 + wc] = mx1;
        }
    }
}

// ===========================================================================
// Fused softmax + PV (fp16 HMMA, cp.async pipeline) — unchanged from R11
// ===========================================================================
#define TSF 68
#define PSTR 36
#define PV_OFF_PS (2 * 128 * TSF)
#define PV_OFF_GS (PV_OFF_PS + 128 * PSTR)
#define PV_OFF_ST (PV_OFF_GS + 128 * PSTR)
#define PV_SMEM_FLOATS (PV_OFF_ST + 2 * 128)

__global__ __launch_bounds__(256, 2) void pv_kernel()
{
    extern __shared__ float sm[];
    uint32_t* Ps  = (uint32_t*)(sm + PV_OFF_PS);
    uint32_t* Gs  = (uint32_t*)(sm + PV_OFF_GS);
    float*   rowm = sm + PV_OFF_ST;
    float*   rowl = rowm + 128;

    int tid = threadIdx.x;
    int b = blockIdx.y, q0 = blockIdx.x * 128;
    const float*  Sp  = g_S + (size_t)(b * NN + q0) * NM;
    const __half* GpH = g_gPt + (size_t)b * ND * NM;

    int lane = tid & 31, g = lane >> 2, t = lane & 3;
    int wid = tid >> 5, wr = wid >> 1, wc = wid & 1;
    int r0 = wr * 32, c0 = wc * 64;

    uint32_t sbase = smem_u32(sm);
    int cr = tid >> 4, cc = (tid & 15) * 4;

    if (tid < 128) {
        const float* pm = g_pmax + (size_t)(b * NN + q0 + tid) * 32;
        float mx = pm[0];
#pragma unroll
        for (int j = 1; j < 32; j++) mx = fmaxf(mx, pm[j]);
        rowm[tid] = mx;
        rowl[tid] = 0.f;
    }

#pragma unroll
    for (int q = 0; q < 4; q++) {
        int idx = q * 256 + tid, r = idx >> 3, hs = (idx & 7) * 8;
        cp_async16(sbase + (PV_OFF_GS + r * PSTR) * 4 + hs * 2, GpH + (size_t)r * NM + hs);
    }
#pragma unroll
    for (int q = 0; q < 8; q++) {
        int r = q * 16 + cr;
        cp_async16(sbase + (r * TSF + cc) * 4, Sp + (size_t)r * NM + cc);
    }
    CP_COMMIT();
#pragma unroll
    for (int q = 0; q < 8; q++) {
        int r = q * 16 + cr;
        cp_async16(sbase + (128 * TSF + r * TSF + cc) * 4, Sp + (size_t)r * NM + 64 + cc);
    }
    CP_COMMIT();

    float yacc[2][8][4];
#pragma unroll
    for (int mt = 0; mt < 2; mt++)
#pragma unroll
        for (int nt = 0; nt < 8; nt++)
#pragma unroll
            for (int i = 0; i < 4; i++) yacc[mt][nt][i] = 0.f;

    int erow = tid >> 1, ecol = (tid & 1) * 32;

#pragma unroll 1
    for (int ch = 0; ch < 32; ch++) {
        int cur = ch & 1;
        float* Ss = sm + cur * 128 * TSF;

        CP_WAIT1();
        __syncthreads();

        {
            float nm = rowm[erow];
            const float* src = Ss + erow * TSF + ecol;
            uint32_t* dst = Ps + erow * PSTR + (ecol >> 1);
            float sum = 0.f;
#pragma unroll
            for (int j = 0; j < 8; j++) {
                float4 v = *(const float4*)(src + j * 4);
                float p0 = __expf(v.x - nm), p1 = __expf(v.y - nm);
                float p2 = __expf(v.z - nm), p3 = __expf(v.w - nm);
                sum += p0 + p1 + p2 + p3;
                __half2 h01 = __floats2half2_rn(p0, p1);
                __half2 h23 = __floats2half2_rn(p2, p3);
                dst[j * 2]     = *(uint32_t*)&h01;
                dst[j * 2 + 1] = *(uint32_t*)&h23;
            }
            sum += __shfl_xor_sync(0xFFFFFFFF, sum, 1);
            if ((tid & 1) == 0) rowl[erow] += sum;
        }
        __syncthreads();

        if (ch + 2 < 32) {
            int m2 = (ch + 2) * 64;
#pragma unroll
            for (int q = 0; q < 8; q++) {
                int r = q * 16 + cr;
                cp_async16(sbase + (cur * 128 * TSF + r * TSF + cc) * 4,
                           Sp + (size_t)r * NM + m2 + cc);
            }
        }

#pragma unroll
        for (int kst = 0; kst < 4; kst++) {
            int kh = kst * 8;
            uint32_t a[2][4];
#pragma unroll
            for (int mt = 0; mt < 2; mt++) {
                const uint32_t* ab = Ps + (r0 + 16 * mt + g) * PSTR + kh + t;
                a[mt][0] = ab[0];
                a[mt][1] = ab[8 * PSTR];
                a[mt][2] = ab[4];
                a[mt][3] = ab[8 * PSTR + 4];
            }
#pragma unroll
            for (int nt = 0; nt < 8; nt++) {
                const uint32_t* gb = Gs + (c0 + 8 * nt + g) * PSTR + kh + t;
                uint32_t b0 = gb[0], b1 = gb[4];
#pragma unroll
                for (int mt = 0; mt < 2; mt++)
                    mma_f16(yacc[mt][nt], a[mt][0], a[mt][1], a[mt][2], a[mt][3], b0, b1);
            }
        }
        __syncthreads();

        if (ch + 1 < 32) {
            int m1 = (ch + 1) * 64;
#pragma unroll
            for (int q = 0; q < 4; q++) {
                int idx = q * 256 + tid, r = idx >> 3, hs = (idx & 7) * 8;
                cp_async16(sbase + (PV_OFF_GS + r * PSTR) * 4 + hs * 2,
                           GpH + (size_t)r * NM + m1 + hs);
            }
        }
        CP_COMMIT();
        CP_COMMIT();
    }

    __syncthreads();
#pragma unroll
    for (int mt = 0; mt < 2; mt++) {
        int ra = r0 + 16 * mt + g, rb = ra + 8;
        float ia = 1.f / rowl[ra], ib = 1.f / rowl[rb];
        float* Y0 = g_y + (size_t)(b * NN + q0 + ra) * ND + c0;
        float* Y1 = g_y + (size_t)(b * NN + q0 + rb) * ND + c0;
#pragma unroll
        for (int nt = 0; nt < 8; nt++) {
            *(float2*)(Y0 + 8 * nt + 2 * t) = make_float2(yacc[mt][nt][0] * ia, yacc[mt][nt][1] * ia);
            *(float2*)(Y1 + 8 * nt + 2 * t) = make_float2(yacc[mt][nt][2] * ib, yacc[mt][nt][3] * ib);
        }
    }
}

// ===========================================================================
// Output GEMM + residual (split-fp16): out = x + y @ Wout
// ===========================================================================
__global__ __launch_bounds__(256, 2) void out_kernel(
    const float* __restrict__ x, const float* __restrict__ Wout, float* __restrict__ out)
{
    extern __shared__ uint32_t smu[];

    int tid = threadIdx.x, row0 = blockIdx.x * 128, col0 = blockIdx.y * 128;
    int lane = tid & 31, g = lane >> 2, t = lane & 3;
    int wid = tid >> 5, wr = wid >> 1, wc = wid & 1;
    int r0 = wr * 32, c0 = wc * 64;

    float acc[2][8][4];
#pragma unroll
    for (int mt = 0; mt < 2; mt++)
#pragma unroll
        for (int nt = 0; nt < 8; nt++)
#pragma unroll
            for (int i = 0; i < 4; i++) acc[mt][nt][i] = 0.f;

#pragma unroll 1
    for (int kc = 0; kc < 2; kc++) {
        int k0 = kc * 64;
        __syncthreads();
#pragma unroll
        for (int q = 0; q < 8; q++) {
            int li = q * 256 + tid, r = li >> 4, c = (li & 15) * 4;
            float4 v = *(const float4*)(g_y + (size_t)(row0 + r) * ND + k0 + c);
            uint2 hi, lo; split4(v, hi, lo);
            *(uint2*)&smu[OFF_AH + r * W36 + (c >> 1)] = hi;
            *(uint2*)&smu[OFF_AL + r * W36 + (c >> 1)] = lo;
        }
#pragma unroll
        for (int q = 0; q < 8; q++) {
            int li = q * 256 + tid, n = li & 127, kq = li >> 7;
            float4 v;
            v.x = Wout[(size_t)(k0 + kq * 4 + 0) * NC + col0 + n];
            v.y = Wout[(size_t)(k0 + kq * 4 + 1) * NC + col0 + n];
            v.z = Wout[(size_t)(k0 + kq * 4 + 2) * NC + col0 + n];
            v.w = Wout[(size_t)(k0 + kq * 4 + 3) * NC + col0 + n];
            uint2 hi, lo; split4(v, hi, lo);
            *(uint2*)&smu[OFF_BH + n * W36 + kq * 2] = hi;
            *(uint2*)&smu[OFF_BL + n * W36 + kq * 2] = lo;
        }
        __syncthreads();
        GEMM_MAINLOOP(smu)
    }
#pragma unroll
    for (int mt = 0; mt < 2; mt++) {
        int ra = row0 + r0 + 16 * mt + g;
        const float* X0 = x + (size_t)ra * NC + col0 + c0;
        const float* X1 = X0 + 8 * (size_t)NC;
        float* O0 = out + (size_t)ra * NC + col0 + c0;
        float* O1 = O0 + 8 * (size_t)NC;
#pragma unroll
        for (int nt = 0; nt < 8; nt++) {
            int cc = 8 * nt + 2 * t;
            float2 x0 = *(const float2*)(X0 + cc);
            float2 x1 = *(const float2*)(X1 + cc);
            *(float2*)(O0 + cc) = make_float2(acc[mt][nt][0] + x0.x, acc[mt][nt][1] + x0.y);
            *(float2*)(O1 + cc) = make_float2(acc[mt][nt][2] + x1.x, acc[mt][nt][3] + x1.y);
        }
    }
}

// ---------------------------------------------------------------------------
extern "C" void kernel_launch(void* const* d_in, const int* in_sizes, int n_in,
                              void* d_out, int out_size)
{
    const float* x  = (const float*)d_in[0];
    const float* Wt = (const float*)d_in[1];
    const float* Wp = (const float*)d_in[2];
    const float* Wg = (const float*)d_in[3];
    const float* Wo = (const float*)d_in[4];
    float* out      = (float*)d_out;

    const int GEMM_SMEM = GEMM_SMEM_U32 * 4;     // 73728 B... (u32 count * 4)
    const int PV_SMEM   = PV_SMEM_FLOATS * 4;    // 107520 B
    cudaFuncSetAttribute(proj_kernel, cudaFuncAttributeMaxDynamicSharedMemorySize, GEMM_SMEM);
    cudaFuncSetAttribute(qk_kernel,   cudaFuncAttributeMaxDynamicSharedMemorySize, GEMM_SMEM);
    cudaFuncSetAttribute(pv_kernel,   cudaFuncAttributeMaxDynamicSharedMemorySize, PV_SMEM);
    cudaFuncSetAttribute(out_kernel,  cudaFuncAttributeMaxDynamicSharedMemorySize, GEMM_SMEM);

    proj_kernel<<<dim3(256, 1, 3), 256, GEMM_SMEM>>>(x, Wt, Wp, Wg);
    pool_kernel<<<(NB * NM * ND / 4 + 255) / 256, 256>>>();
    qk_kernel<<<dim3(32, 16, 8), 256, GEMM_SMEM>>>();
    pv_kernel<<<dim3(32, 8), 256, PV_SMEM>>>();
    out_kernel<<<dim3(256, 2), 256, GEMM_SMEM>>>(x, Wo, out);
}